// round 6
// baseline (speedup 1.0000x reference)
#include <cuda_runtime.h>
#include <math.h>
#include <stdint.h>

#define BB     4
#define LSEQ   1024
#define INDIM  256
#define DM     512
#define NH     8
#define DHD    64
#define FFD    2048
#define NTOK   (BB*LSEQ)   // 4096

// ---------------- scratch (device globals: allocation-free) ----------------
__device__ float g_x   [NTOK*DM];
__device__ float g_xn  [NTOK*DM];
__device__ float g_qkv [NTOK*3*DM];
__device__ float g_ctx [NTOK*DM];
__device__ float g_h   [NTOK*FFD];
__device__ unsigned char g_rowall[NTOK];

__device__ __forceinline__ uint32_t tf32r(float x) {
    uint32_t r; asm("cvt.rna.tf32.f32 %0, %1;" : "=r"(r) : "f"(x)); return r;
}
__device__ __forceinline__ void mma_tf32(float* c,
    uint32_t a0, uint32_t a1, uint32_t a2, uint32_t a3,
    uint32_t b0, uint32_t b1) {
    asm volatile(
        "mma.sync.aligned.m16n8k8.row.col.f32.tf32.tf32.f32 "
        "{%0,%1,%2,%3}, {%4,%5,%6,%7}, {%8,%9}, {%0,%1,%2,%3};"
        : "+f"(c[0]), "+f"(c[1]), "+f"(c[2]), "+f"(c[3])
        : "r"(a0), "r"(a1), "r"(a2), "r"(a3), "r"(b0), "r"(b1));
}

// ================= tf32 mma.sync GEMM =================
// 512 threads, 16 warps 4(m) x 4(n), warp tile 32x32 -> acc 32 regs/thread.
// BM=BN=128, BK=32; permuted-K smem [row][perm(k)], perm(k)=(k&3)*8+(k>>2), pad 36.
// Double-buffered, one __syncthreads per chunk, global prefetch + mid-compute staging.
#define RPAD 36
#define STGU (2 * 128 * RPAD)          // uint32s per stage (A+B)

template<int EPI>
__global__ __launch_bounds__(512, 1) void mma_gemm(
    const float* __restrict__ A, const float* __restrict__ W,
    const float* __restrict__ bias, const float* __restrict__ res,
    float* __restrict__ C, int M, int N, int K)
{
    extern __shared__ uint32_t smem_[];
    const int tid = threadIdx.x;
    const int bm = blockIdx.y * 128, bn = blockIdx.x * 128;
    const int lane = tid & 31, warp = tid >> 5;
    const int wm = warp & 3, wn = warp >> 2;
    const int m_base = wm * 32, n_base = wn * 32;
    const int lg = lane >> 2, lt = lane & 3;

    float acc[2][4][4];
    #pragma unroll
    for (int mt = 0; mt < 2; mt++)
        #pragma unroll
        for (int nt = 0; nt < 4; nt++)
            #pragma unroll
            for (int q = 0; q < 4; q++) acc[mt][nt][q] = 0.f;

    // global map: 512 thr = 64 rows x 8 kc; each thread rows r0, r0+64
    const int r0 = tid >> 3, kc = tid & 7;
    const float* Ab = A + (size_t)(bm + r0) * K + kc * 4;
    const float* Bb = W + (size_t)(bn + r0) * K + kc * 4;
    const size_t rstep = (size_t)64 * K;
    const int nc = K / 32;

    float4 ra[2], rb[2];
    #pragma unroll
    for (int i = 0; i < 2; i++) {
        ra[i] = *(const float4*)(Ab + i * rstep);
        rb[i] = *(const float4*)(Bb + i * rstep);
    }
    {   // prologue: stage 0
        uint32_t* As0 = smem_;
        uint32_t* Bs0 = smem_ + 128 * RPAD;
        #pragma unroll
        for (int i = 0; i < 2; i++) {
            uint32_t* arow = As0 + (r0 + i * 64) * RPAD + kc;
            uint32_t* brow = Bs0 + (r0 + i * 64) * RPAD + kc;
            arow[0] = tf32r(ra[i].x); arow[8] = tf32r(ra[i].y);
            arow[16] = tf32r(ra[i].z); arow[24] = tf32r(ra[i].w);
            brow[0] = tf32r(rb[i].x); brow[8] = tf32r(rb[i].y);
            brow[16] = tf32r(rb[i].z); brow[24] = tf32r(rb[i].w);
        }
    }
    __syncthreads();

    for (int c = 0; c < nc; c++) {
        const uint32_t* As = smem_ + (c & 1) * STGU;
        const uint32_t* Bs = As + 128 * RPAD;
        uint32_t* Asn = smem_ + ((c + 1) & 1) * STGU;
        uint32_t* Bsn = Asn + 128 * RPAD;
        const bool pf = (c + 1 < nc);

        if (pf) {
            #pragma unroll
            for (int i = 0; i < 2; i++) {
                ra[i] = *(const float4*)(Ab + i * rstep + (c + 1) * 32);
                rb[i] = *(const float4*)(Bb + i * rstep + (c + 1) * 32);
            }
        }

        // A fragments: 8 k-values per row = 2 contiguous uint4
        uint32_t arw[2][2][8];
        #pragma unroll
        for (int mt = 0; mt < 2; mt++) {
            const int mr = m_base + mt * 16 + lg;
            *(uint4*)&arw[mt][0][0] = *(const uint4*)(As + mr * RPAD + lt * 8);
            *(uint4*)&arw[mt][0][4] = *(const uint4*)(As + mr * RPAD + lt * 8 + 4);
            *(uint4*)&arw[mt][1][0] = *(const uint4*)(As + (mr + 8) * RPAD + lt * 8);
            *(uint4*)&arw[mt][1][4] = *(const uint4*)(As + (mr + 8) * RPAD + lt * 8 + 4);
        }

        #pragma unroll
        for (int nt = 0; nt < 4; nt++) {
            if (nt == 1 && pf) {
                #pragma unroll
                for (int i = 0; i < 2; i++) {
                    uint32_t* arow = Asn + (r0 + i * 64) * RPAD + kc;
                    arow[0] = tf32r(ra[i].x); arow[8] = tf32r(ra[i].y);
                    arow[16] = tf32r(ra[i].z); arow[24] = tf32r(ra[i].w);
                }
            }
            if (nt == 3 && pf) {
                #pragma unroll
                for (int i = 0; i < 2; i++) {
                    uint32_t* brow = Bsn + (r0 + i * 64) * RPAD + kc;
                    brow[0] = tf32r(rb[i].x); brow[8] = tf32r(rb[i].y);
                    brow[16] = tf32r(rb[i].z); brow[24] = tf32r(rb[i].w);
                }
            }
            const int nr = n_base + nt * 8 + lg;
            uint32_t brw[8];
            *(uint4*)&brw[0] = *(const uint4*)(Bs + nr * RPAD + lt * 8);
            *(uint4*)&brw[4] = *(const uint4*)(Bs + nr * RPAD + lt * 8 + 4);
            #pragma unroll
            for (int ks = 0; ks < 4; ks++) {
                #pragma unroll
                for (int mt = 0; mt < 2; mt++)
                    mma_tf32(acc[mt][nt],
                             arw[mt][0][2*ks], arw[mt][1][2*ks],
                             arw[mt][0][2*ks+1], arw[mt][1][2*ks+1],
                             brw[2*ks], brw[2*ks+1]);
            }
        }
        __syncthreads();
    }

    // epilogue
    #pragma unroll
    for (int mt = 0; mt < 2; mt++) {
        #pragma unroll
        for (int nt = 0; nt < 4; nt++) {
            const int row = bm + m_base + mt * 16 + lg;
            const int col = bn + n_base + nt * 8 + lt * 2;
            #pragma unroll
            for (int half = 0; half < 2; half++) {
                const int r = row + half * 8;
                float v0 = acc[mt][nt][half*2+0] + bias[col];
                float v1 = acc[mt][nt][half*2+1] + bias[col+1];
                if (EPI == 1) {
                    v0 = 0.5f * v0 * (1.f + erff(v0 * 0.70710678118654752f));
                    v1 = 0.5f * v1 * (1.f + erff(v1 * 0.70710678118654752f));
                }
                if (EPI == 2) {
                    float2 rr = *(const float2*)(res + (size_t)r * N + col);
                    v0 += rr.x; v1 += rr.y;
                }
                *(float2*)(C + (size_t)r * N + col) = make_float2(v0, v1);
            }
        }
    }
}

// ---------------- layernorm ----------------
__global__ __launch_bounds__(128) void ln_kernel(
    const float* __restrict__ X, const float* __restrict__ g,
    const float* __restrict__ b, float* __restrict__ Y)
{
    const int row = blockIdx.x;
    const int tid = threadIdx.x;
    float4 v = *(const float4*)(X + (size_t)row*DM + tid*4);
    float s  = v.x + v.y + v.z + v.w;
    float s2 = v.x*v.x + v.y*v.y + v.z*v.z + v.w*v.w;
    #pragma unroll
    for (int off = 16; off >= 1; off >>= 1) {
        s  += __shfl_xor_sync(0xffffffffu, s,  off);
        s2 += __shfl_xor_sync(0xffffffffu, s2, off);
    }
    __shared__ float sh[8];
    if ((tid & 31) == 0) { sh[tid>>5] = s; sh[4 + (tid>>5)] = s2; }
    __syncthreads();
    s  = sh[0] + sh[1] + sh[2] + sh[3];
    s2 = sh[4] + sh[5] + sh[6] + sh[7];
    float mu  = s * (1.f/DM);
    float var = s2 * (1.f/DM) - mu*mu;
    float inv = rsqrtf(var + 1e-5f);
    float4 gg = *(const float4*)(g + tid*4);
    float4 bb = *(const float4*)(b + tid*4);
    float4 y;
    y.x = (v.x - mu)*inv*gg.x + bb.x;
    y.y = (v.y - mu)*inv*gg.y + bb.y;
    y.z = (v.z - mu)*inv*gg.z + bb.z;
    y.w = (v.w - mu)*inv*gg.w + bb.w;
    *(float4*)(Y + (size_t)row*DM + tid*4) = y;
}

// ---------------- row_all (mask int32 0/1) ----------------
__global__ __launch_bounds__(128) void rowall_kernel(
    const int* __restrict__ mask, unsigned char* __restrict__ out)
{
    const int row = blockIdx.x;
    const int tid = threadIdx.x;
    const int* m = mask + (size_t)row * LSEQ;
    int mn = 1;
    #pragma unroll
    for (int c = 0; c < LSEQ / 512; c++) {
        int4 v = *(const int4*)(m + c*512 + tid*4);
        mn = min(mn, min(min(v.x, v.y), min(v.z, v.w)));
    }
    #pragma unroll
    for (int off = 16; off >= 1; off >>= 1)
        mn = min(mn, __shfl_xor_sync(0xffffffffu, mn, off));
    __shared__ int sh[4];
    if ((tid & 31) == 0) sh[tid>>5] = mn;
    __syncthreads();
    if (tid == 0) {
        int r = min(min(sh[0], sh[1]), min(sh[2], sh[3]));
        out[row] = (r != 0) ? 1 : 0;
    }
}

// ---------------- flash attention with inline bias (fp32 SIMT) ----------------
__global__ __launch_bounds__(256) void attn_kernel(
    const float* __restrict__ qkv,
    const int* __restrict__ mask,
    const float* __restrict__ adj,
    const unsigned char* __restrict__ rowall,
    const float* __restrict__ logscale,
    float* __restrict__ ctx)
{
    __shared__ float Qts[64][64];
    __shared__ float KP [64][64];
    __shared__ float Vs [64][64];
    const int b = blockIdx.z, h = blockIdx.y;
    const int q0 = blockIdx.x * 64;
    const int tid = threadIdx.x;
    const int tx = tid & 15, ty = tid >> 4;
    const float escale = expf(logscale[0]);
    const int lr = tid >> 2;
    const int lc = (tid & 3) << 2;

    {
        const float* qg = qkv + (size_t)(b*LSEQ + q0 + lr)*(3*DM) + h*DHD;
        #pragma unroll
        for (int dd = 0; dd < DHD; dd += 16) {
            float4 v = *(const float4*)(qg + dd + lc);
            Qts[dd+lc+0][lr] = v.x; Qts[dd+lc+1][lr] = v.y;
            Qts[dd+lc+2][lr] = v.z; Qts[dd+lc+3][lr] = v.w;
        }
    }
    const int qr0 = ty * 4;
    const int cc0 = tx * 4;

    float o[4][4], mi[4], li[4];
    #pragma unroll
    for (int i = 0; i < 4; i++) {
        mi[i] = -1e30f; li[i] = 0.f;
        #pragma unroll
        for (int j = 0; j < 4; j++) o[i][j] = 0.f;
    }
    bool ra[4];
    #pragma unroll
    for (int i = 0; i < 4; i++) ra[i] = rowall[b*LSEQ + q0 + qr0 + i] != 0;

    for (int k0 = 0; k0 < LSEQ; k0 += 64) {
        const float* kg = qkv + (size_t)(b*LSEQ + k0 + lr)*(3*DM) + DM + h*DHD;
        const float* vg = kg + DM;
        #pragma unroll
        for (int dd = 0; dd < DHD; dd += 16) {
            float4 kv = *(const float4*)(kg + dd + lc);
            KP[dd+lc+0][lr] = kv.x; KP[dd+lc+1][lr] = kv.y;
            KP[dd+lc+2][lr] = kv.z; KP[dd+lc+3][lr] = kv.w;
            float4 vv = *(const float4*)(vg + dd + lc);
            *(float4*)&Vs[lr][dd+lc] = vv;
        }
        __syncthreads();

        float s[4][4];
        #pragma unroll
        for (int i = 0; i < 4; i++)
            #pragma unroll
            for (int j = 0; j < 4; j++) s[i][j] = 0.f;
        #pragma unroll
        for (int d = 0; d < DHD; d++) {
            float4 rq = *(const float4*)&Qts[d][qr0];
            float4 rk = *(const float4*)&KP[d][cc0];
            float q_[4] = {rq.x, rq.y, rq.z, rq.w};
            float k_[4] = {rk.x, rk.y, rk.z, rk.w};
            #pragma unroll
            for (int i = 0; i < 4; i++)
                #pragma unroll
                for (int j = 0; j < 4; j++) s[i][j] += q_[i]*k_[j];
        }

        #pragma unroll
        for (int i = 0; i < 4; i++) {
            const int q = q0 + qr0 + i;
            const size_t rowoff = ((size_t)b*LSEQ + q)*LSEQ + k0 + cc0;
            const int4 mi4 = *(const int4*)(mask + rowoff);
            const float4 ad4 = *(const float4*)(adj + rowoff);
            int   mm_[4] = {mi4.x, mi4.y, mi4.z, mi4.w};
            float ad_[4] = {ad4.x, ad4.y, ad4.z, ad4.w};
            float rowmax = -1e30f;
            #pragma unroll
            for (int j = 0; j < 4; j++) {
                int kk = k0 + cc0 + j;
                float ad = fminf(fmaxf(ad_[j], 0.f), 1.f);
                bool eff = (mm_[j] != 0) && !((kk == q) && ra[i]);
                float val = s[i][j]*0.125f + (eff ? -10000.f : 0.f) + escale*ad;
                s[i][j] = val;
                rowmax = fmaxf(rowmax, val);
            }
            #pragma unroll
            for (int off = 8; off >= 1; off >>= 1)
                rowmax = fmaxf(rowmax, __shfl_xor_sync(0xffffffffu, rowmax, off));
            float mnew = fmaxf(mi[i], rowmax);
            float corr = expf(mi[i] - mnew);
            float psum = 0.f;
            #pragma unroll
            for (int j = 0; j < 4; j++) {
                float p = expf(s[i][j] - mnew);
                s[i][j] = p; psum += p;
            }
            #pragma unroll
            for (int off = 8; off >= 1; off >>= 1)
                psum += __shfl_xor_sync(0xffffffffu, psum, off);
            li[i] = li[i]*corr + psum;
            #pragma unroll
            for (int j = 0; j < 4; j++) o[i][j] *= corr;
            mi[i] = mnew;
        }
        __syncthreads();

        #pragma unroll
        for (int i = 0; i < 4; i++)
            #pragma unroll
            for (int j = 0; j < 4; j++) KP[qr0+i][cc0+j] = s[i][j];
        __syncthreads();

        #pragma unroll
        for (int k = 0; k < 64; k++) {
            float4 rv = *(const float4*)&Vs[k][cc0];
            float v_[4] = {rv.x, rv.y, rv.z, rv.w};
            float p0 = KP[qr0+0][k], p1 = KP[qr0+1][k];
            float p2 = KP[qr0+2][k], p3 = KP[qr0+3][k];
            #pragma unroll
            for (int j = 0; j < 4; j++) {
                o[0][j] += p0*v_[j]; o[1][j] += p1*v_[j];
                o[2][j] += p2*v_[j]; o[3][j] += p3*v_[j];
            }
        }
        __syncthreads();
    }

    #pragma unroll
    for (int i = 0; i < 4; i++) {
        float inv = 1.f / li[i];
        #pragma unroll
        for (int j = 0; j < 4; j++) {
            ctx[(size_t)(b*LSEQ + q0 + qr0 + i)*DM + h*DHD + cc0 + j] = o[i][j]*inv;
        }
    }
}

// ---------------- launch ----------------
extern "C" void kernel_launch(void* const* d_in, const int* in_sizes, int n_in,
                              void* d_out, int out_size)
{
    (void)in_sizes; (void)n_in; (void)out_size;
    const float* x      = (const float*)d_in[0];
    const int*   amask  = (const int*)d_in[1];
    const float* adj    = (const float*)d_in[2];
    const float* Wf     = (const float*)d_in[3];
    const float* bf     = (const float*)d_in[4];
    const float* Wqkv   = (const float*)d_in[5];
    const float* bqkv   = (const float*)d_in[6];
    const float* Wo     = (const float*)d_in[7];
    const float* bo     = (const float*)d_in[8];
    const float* ln1g   = (const float*)d_in[9];
    const float* ln1b   = (const float*)d_in[10];
    const float* ln2g   = (const float*)d_in[11];
    const float* ln2b   = (const float*)d_in[12];
    const float* W1     = (const float*)d_in[13];
    const float* b1     = (const float*)d_in[14];
    const float* W2     = (const float*)d_in[15];
    const float* b2     = (const float*)d_in[16];
    const float* lscale = (const float*)d_in[17];
    float* out = (float*)d_out;

    float *gx, *gxn, *gqkv, *gctx, *gh;
    unsigned char* grow;
    cudaGetSymbolAddress((void**)&gx,   g_x);
    cudaGetSymbolAddress((void**)&gxn,  g_xn);
    cudaGetSymbolAddress((void**)&gqkv, g_qkv);
    cudaGetSymbolAddress((void**)&gctx, g_ctx);
    cudaGetSymbolAddress((void**)&gh,   g_h);
    cudaGetSymbolAddress((void**)&grow, g_rowall);

    const int SMB = 2 * STGU * 4;   // 73728 bytes
    cudaFuncSetAttribute((const void*)mma_gemm<0>, cudaFuncAttributeMaxDynamicSharedMemorySize, SMB);
    cudaFuncSetAttribute((const void*)mma_gemm<1>, cudaFuncAttributeMaxDynamicSharedMemorySize, SMB);
    cudaFuncSetAttribute((const void*)mma_gemm<2>, cudaFuncAttributeMaxDynamicSharedMemorySize, SMB);

    // 1. fuse projection: g_x = x @ Wf^T + bf
    mma_gemm<0><<<dim3(DM/128, NTOK/128), 512, SMB>>>(x, Wf, bf, nullptr, gx, NTOK, DM, INDIM);
    // 2. row_all
    rowall_kernel<<<NTOK, 128>>>(amask, grow);
    // 3. LN1
    ln_kernel<<<NTOK, 128>>>(gx, ln1g, ln1b, gxn);
    // 4. qkv
    mma_gemm<0><<<dim3((3*DM)/128, NTOK/128), 512, SMB>>>(gxn, Wqkv, bqkv, nullptr, gqkv, NTOK, 3*DM, DM);
    // 5. attention
    attn_kernel<<<dim3(LSEQ/64, NH, BB), 256>>>(gqkv, amask, adj, grow, lscale, gctx);
    // 6. out proj + residual
    mma_gemm<2><<<dim3(DM/128, NTOK/128), 512, SMB>>>(gctx, Wo, bo, gx, gx, NTOK, DM, DM);
    // 7. LN2
    ln_kernel<<<NTOK, 128>>>(gx, ln2g, ln2b, gxn);
    // 8. FFN up + GELU
    mma_gemm<1><<<dim3(FFD/128, NTOK/128), 512, SMB>>>(gxn, W1, b1, nullptr, gh, NTOK, FFD, DM);
    // 9. FFN down + residual -> out
    mma_gemm<2><<<dim3(DM/128, NTOK/128), 512, SMB>>>(gh, W2, b2, gx, out, NTOK, DM, FFD);
}

// round 7
// speedup vs baseline: 1.5389x; 1.5389x over previous
#include <cuda_runtime.h>
#include <math.h>
#include <stdint.h>

#define BB     4
#define LSEQ   1024
#define INDIM  256
#define DM     512
#define NH     8
#define DHD    64
#define FFD    2048
#define NTOK   (BB*LSEQ)   // 4096

// ---------------- scratch (device globals: allocation-free) ----------------
__device__ float g_x   [NTOK*DM];
__device__ float g_xn  [NTOK*DM];
__device__ float g_qkv [NTOK*3*DM];
__device__ float g_ctx [NTOK*DM];
__device__ float g_h   [NTOK*FFD];
__device__ unsigned char g_rowall[NTOK];

__device__ __forceinline__ uint32_t tf32r(float x) {
    uint32_t r; asm("cvt.rna.tf32.f32 %0, %1;" : "=r"(r) : "f"(x)); return r;
}
__device__ __forceinline__ void mma_tf32(float* c, const uint32_t* a, const uint32_t* b) {
    asm volatile(
        "mma.sync.aligned.m16n8k8.row.col.f32.tf32.tf32.f32 "
        "{%0,%1,%2,%3}, {%4,%5,%6,%7}, {%8,%9}, {%0,%1,%2,%3};"
        : "+f"(c[0]), "+f"(c[1]), "+f"(c[2]), "+f"(c[3])
        : "r"(a[0]), "r"(a[1]), "r"(a[2]), "r"(a[3]), "r"(b[0]), "r"(b[1]));
}

// ================= tf32 mma.sync GEMM (R4 config — best measured) =================
// C[M,N] = A[M,K] @ W[N,K]^T + bias[N]  (EPI: 0=bias, 1=+exact GELU, 2=+residual)
// BM=BN=128, BK=32; 8 warps in 4(m) x 2(n) grid; warp tile 32m x 64n.
template<int EPI>
__global__ __launch_bounds__(256, 2) void mma_gemm(
    const float* __restrict__ A, const float* __restrict__ W,
    const float* __restrict__ bias, const float* __restrict__ res,
    float* __restrict__ C, int M, int N, int K)
{
    __shared__ uint32_t As[32][132];   // [k][m], tf32 bits
    __shared__ uint32_t Bs[32][132];   // [k][n]
    const int tid = threadIdx.x;
    const int bm = blockIdx.y * 128, bn = blockIdx.x * 128;
    const int lane = tid & 31, warp = tid >> 5;
    const int wm = warp & 3, wn = warp >> 2;
    const int m_base = wm * 32, n_base = wn * 64;
    const int lg = lane >> 2, lt = lane & 3;

    float acc[2][8][4];
    #pragma unroll
    for (int mt = 0; mt < 2; mt++)
        #pragma unroll
        for (int nt = 0; nt < 8; nt++)
            #pragma unroll
            for (int q = 0; q < 4; q++) acc[mt][nt][q] = 0.f;

    int am[4], akc[4];
    const float4* Ag[4];
    const float4* Bg[4];
    #pragma unroll
    for (int i = 0; i < 4; i++) {
        int f = i * 256 + tid;
        am[i] = f >> 3; akc[i] = f & 7;
        Ag[i] = (const float4*)(A + (size_t)(bm + am[i]) * K) + akc[i];
        Bg[i] = (const float4*)(W + (size_t)(bn + am[i]) * K) + akc[i];
    }

    const int nc = K / 32;
    for (int c = 0; c < nc; c++) {
        #pragma unroll
        for (int i = 0; i < 4; i++) {
            float4 va = Ag[i][c * 8];
            float4 vb = Bg[i][c * 8];
            int kk = akc[i] * 4, m = am[i];
            As[kk+0][m] = tf32r(va.x); As[kk+1][m] = tf32r(va.y);
            As[kk+2][m] = tf32r(va.z); As[kk+3][m] = tf32r(va.w);
            Bs[kk+0][m] = tf32r(vb.x); Bs[kk+1][m] = tf32r(vb.y);
            Bs[kk+2][m] = tf32r(vb.z); Bs[kk+3][m] = tf32r(vb.w);
        }
        __syncthreads();
        #pragma unroll
        for (int ks = 0; ks < 4; ks++) {
            const int k = ks * 8;
            uint32_t a[2][4], b[8][2];
            #pragma unroll
            for (int mt = 0; mt < 2; mt++) {
                int mr = m_base + mt * 16 + lg;
                a[mt][0] = As[k + lt    ][mr];
                a[mt][1] = As[k + lt    ][mr + 8];
                a[mt][2] = As[k + lt + 4][mr];
                a[mt][3] = As[k + lt + 4][mr + 8];
            }
            #pragma unroll
            for (int nt = 0; nt < 8; nt++) {
                int nr = n_base + nt * 8 + lg;
                b[nt][0] = Bs[k + lt    ][nr];
                b[nt][1] = Bs[k + lt + 4][nr];
            }
            #pragma unroll
            for (int mt = 0; mt < 2; mt++)
                #pragma unroll
                for (int nt = 0; nt < 8; nt++)
                    mma_tf32(acc[mt][nt], a[mt], b[nt]);
        }
        __syncthreads();
    }

    #pragma unroll
    for (int mt = 0; mt < 2; mt++) {
        #pragma unroll
        for (int nt = 0; nt < 8; nt++) {
            const int row = bm + m_base + mt * 16 + lg;
            const int col = bn + n_base + nt * 8 + lt * 2;
            #pragma unroll
            for (int half = 0; half < 2; half++) {
                const int r = row + half * 8;
                float v0 = acc[mt][nt][half*2+0] + bias[col];
                float v1 = acc[mt][nt][half*2+1] + bias[col+1];
                if (EPI == 1) {
                    v0 = 0.5f * v0 * (1.f + erff(v0 * 0.70710678118654752f));
                    v1 = 0.5f * v1 * (1.f + erff(v1 * 0.70710678118654752f));
                }
                if (EPI == 2) {
                    float2 rr = *(const float2*)(res + (size_t)r * N + col);
                    v0 += rr.x; v1 += rr.y;
                }
                *(float2*)(C + (size_t)r * N + col) = make_float2(v0, v1);
            }
        }
    }
}

// ---------------- layernorm ----------------
__global__ __launch_bounds__(128) void ln_kernel(
    const float* __restrict__ X, const float* __restrict__ g,
    const float* __restrict__ b, float* __restrict__ Y)
{
    const int row = blockIdx.x;
    const int tid = threadIdx.x;
    float4 v = *(const float4*)(X + (size_t)row*DM + tid*4);
    float s  = v.x + v.y + v.z + v.w;
    float s2 = v.x*v.x + v.y*v.y + v.z*v.z + v.w*v.w;
    #pragma unroll
    for (int off = 16; off >= 1; off >>= 1) {
        s  += __shfl_xor_sync(0xffffffffu, s,  off);
        s2 += __shfl_xor_sync(0xffffffffu, s2, off);
    }
    __shared__ float sh[8];
    if ((tid & 31) == 0) { sh[tid>>5] = s; sh[4 + (tid>>5)] = s2; }
    __syncthreads();
    s  = sh[0] + sh[1] + sh[2] + sh[3];
    s2 = sh[4] + sh[5] + sh[6] + sh[7];
    float mu  = s * (1.f/DM);
    float var = s2 * (1.f/DM) - mu*mu;
    float inv = rsqrtf(var + 1e-5f);
    float4 gg = *(const float4*)(g + tid*4);
    float4 bb = *(const float4*)(b + tid*4);
    float4 y;
    y.x = (v.x - mu)*inv*gg.x + bb.x;
    y.y = (v.y - mu)*inv*gg.y + bb.y;
    y.z = (v.z - mu)*inv*gg.z + bb.z;
    y.w = (v.w - mu)*inv*gg.w + bb.w;
    *(float4*)(Y + (size_t)row*DM + tid*4) = y;
}

// ---------------- row_all (mask int32 0/1) ----------------
__global__ __launch_bounds__(128) void rowall_kernel(
    const int* __restrict__ mask, unsigned char* __restrict__ out)
{
    const int row = blockIdx.x;
    const int tid = threadIdx.x;
    const int* m = mask + (size_t)row * LSEQ;
    int mn = 1;
    #pragma unroll
    for (int c = 0; c < LSEQ / 512; c++) {
        int4 v = *(const int4*)(m + c*512 + tid*4);
        mn = min(mn, min(min(v.x, v.y), min(v.z, v.w)));
    }
    #pragma unroll
    for (int off = 16; off >= 1; off >>= 1)
        mn = min(mn, __shfl_xor_sync(0xffffffffu, mn, off));
    __shared__ int sh[4];
    if ((tid & 31) == 0) sh[tid>>5] = mn;
    __syncthreads();
    if (tid == 0) {
        int r = min(min(sh[0], sh[1]), min(sh[2], sh[3]));
        out[row] = (r != 0) ? 1 : 0;
    }
}

// ---------------- flash attention on tensor pipe (tf32 mma.sync) ----------------
// 64q tile per CTA, 128 threads = 4 warps, warp = 16q x 64k (softmax warp-local).
// smem: Qs[64][68], Ks[64][68], Ps[64][68] (tf32), Vs[64][72] (tf32, row-major).
#define APAD 68
#define VPAD 72
#define SM_Q 0
#define SM_K (64*APAD)
#define SM_P (2*64*APAD)
#define SM_V (3*64*APAD)
#define ATTN_SMEM ((3*64*APAD + 64*VPAD) * 4)

__global__ __launch_bounds__(128) void attn_mma(
    const float* __restrict__ qkv,
    const int* __restrict__ mask,
    const float* __restrict__ adj,
    const unsigned char* __restrict__ rowall,
    const float* __restrict__ logscale,
    float* __restrict__ ctx)
{
    extern __shared__ uint32_t sm[];
    uint32_t* Qs = sm + SM_Q;
    uint32_t* Ks = sm + SM_K;
    uint32_t* Ps = sm + SM_P;
    uint32_t* Vs = sm + SM_V;

    const int b = blockIdx.z, h = blockIdx.y;
    const int q0 = blockIdx.x * 64;
    const int tid = threadIdx.x;
    const int lane = tid & 31, warp = tid >> 5;
    const int lg = lane >> 2, lt = lane & 3;
    const int mb = warp * 16;
    const float escale = expf(logscale[0]);

    // load maps for 64x64 tiles: 2 threads per row, 32 cols each
    const int lrow = tid >> 1, lcb = (tid & 1) * 32;

    // ---- load Q tile (tf32) ----
    {
        const float* qg = qkv + (size_t)(b*LSEQ + q0 + lrow)*(3*DM) + h*DHD + lcb;
        #pragma unroll
        for (int i = 0; i < 8; i++) {
            float4 v = *(const float4*)(qg + i*4);
            uint32_t* dst = Qs + lrow*APAD + lcb + i*4;
            dst[0] = tf32r(v.x); dst[1] = tf32r(v.y);
            dst[2] = tf32r(v.z); dst[3] = tf32r(v.w);
        }
    }
    __syncthreads();

    // ---- hoist Q fragments (constant over KV loop) ----
    uint32_t qa[8][4];
    #pragma unroll
    for (int ks = 0; ks < 8; ks++) {
        const int k8 = ks * 8;
        qa[ks][0] = Qs[(mb+lg  )*APAD + k8 + lt];
        qa[ks][1] = Qs[(mb+lg+8)*APAD + k8 + lt];
        qa[ks][2] = Qs[(mb+lg  )*APAD + k8 + lt + 4];
        qa[ks][3] = Qs[(mb+lg+8)*APAD + k8 + lt + 4];
    }

    float o[8][4];
    #pragma unroll
    for (int nt = 0; nt < 8; nt++)
        #pragma unroll
        for (int q = 0; q < 4; q++) o[nt][q] = 0.f;
    float mi[2] = {-1e30f, -1e30f}, li[2] = {0.f, 0.f};

    const int qrow[2] = { q0 + mb + lg, q0 + mb + lg + 8 };
    const bool raq[2] = { rowall[b*LSEQ + qrow[0]] != 0, rowall[b*LSEQ + qrow[1]] != 0 };

    for (int k0 = 0; k0 < LSEQ; k0 += 64) {
        // ---- load K, V tiles (tf32) ----
        {
            const float* kg = qkv + (size_t)(b*LSEQ + k0 + lrow)*(3*DM) + DM + h*DHD + lcb;
            const float* vg = kg + DM;
            #pragma unroll
            for (int i = 0; i < 8; i++) {
                float4 kv = *(const float4*)(kg + i*4);
                uint32_t* kd = Ks + lrow*APAD + lcb + i*4;
                kd[0] = tf32r(kv.x); kd[1] = tf32r(kv.y);
                kd[2] = tf32r(kv.z); kd[3] = tf32r(kv.w);
                float4 vv = *(const float4*)(vg + i*4);
                uint32_t* vd = Vs + lrow*VPAD + lcb + i*4;
                vd[0] = tf32r(vv.x); vd[1] = tf32r(vv.y);
                vd[2] = tf32r(vv.z); vd[3] = tf32r(vv.w);
            }
        }
        __syncthreads();

        // ---- S = Q @ K^T (64q x 64k per warp row-slice) ----
        float s[8][4];
        #pragma unroll
        for (int nt = 0; nt < 8; nt++)
            #pragma unroll
            for (int q = 0; q < 4; q++) s[nt][q] = 0.f;
        #pragma unroll
        for (int ks = 0; ks < 8; ks++) {
            const int k8 = ks * 8;
            #pragma unroll
            for (int nt = 0; nt < 8; nt++) {
                uint32_t bfr[2];
                bfr[0] = Ks[(nt*8+lg)*APAD + k8 + lt];
                bfr[1] = Ks[(nt*8+lg)*APAD + k8 + lt + 4];
                mma_tf32(s[nt], qa[ks], bfr);
            }
        }

        // ---- bias + online softmax (rows lg, lg+8; warp-local) ----
        #pragma unroll
        for (int r = 0; r < 2; r++) {
            const int q = qrow[r];
            const size_t roff = ((size_t)b*LSEQ + q)*LSEQ + k0;
            float rmax = -1e30f;
            #pragma unroll
            for (int nt = 0; nt < 8; nt++) {
                const int col = nt*8 + lt*2;
                const int2 mm = *(const int2*)(mask + roff + col);
                const float2 ad = *(const float2*)(adj + roff + col);
                float a0 = fminf(fmaxf(ad.x, 0.f), 1.f);
                float a1 = fminf(fmaxf(ad.y, 0.f), 1.f);
                bool e0 = (mm.x != 0) && !((k0+col   == q) && raq[r]);
                bool e1 = (mm.y != 0) && !((k0+col+1 == q) && raq[r]);
                float v0 = s[nt][2*r  ]*0.125f + (e0 ? -10000.f : 0.f) + escale*a0;
                float v1 = s[nt][2*r+1]*0.125f + (e1 ? -10000.f : 0.f) + escale*a1;
                s[nt][2*r  ] = v0; s[nt][2*r+1] = v1;
                rmax = fmaxf(rmax, fmaxf(v0, v1));
            }
            rmax = fmaxf(rmax, __shfl_xor_sync(0xffffffffu, rmax, 1));
            rmax = fmaxf(rmax, __shfl_xor_sync(0xffffffffu, rmax, 2));
            float mnew = fmaxf(mi[r], rmax);
            float corr = __expf(mi[r] - mnew);
            float psum = 0.f;
            #pragma unroll
            for (int nt = 0; nt < 8; nt++) {
                float p0 = __expf(s[nt][2*r  ] - mnew);
                float p1 = __expf(s[nt][2*r+1] - mnew);
                s[nt][2*r] = p0; s[nt][2*r+1] = p1;
                psum += p0 + p1;
            }
            psum += __shfl_xor_sync(0xffffffffu, psum, 1);
            psum += __shfl_xor_sync(0xffffffffu, psum, 2);
            li[r] = li[r]*corr + psum;
            mi[r] = mnew;
            #pragma unroll
            for (int nt = 0; nt < 8; nt++) { o[nt][2*r] *= corr; o[nt][2*r+1] *= corr; }
            // stash P (tf32) for PV mma
            #pragma unroll
            for (int nt = 0; nt < 8; nt++) {
                uint32_t* pd = Ps + (mb+lg+8*r)*APAD + nt*8 + lt*2;
                pd[0] = tf32r(s[nt][2*r]); pd[1] = tf32r(s[nt][2*r+1]);
            }
        }
        __syncthreads();

        // ---- O += P @ V ----
        #pragma unroll
        for (int ks = 0; ks < 8; ks++) {
            const int k8 = ks * 8;
            uint32_t pa[4];
            pa[0] = Ps[(mb+lg  )*APAD + k8 + lt];
            pa[1] = Ps[(mb+lg+8)*APAD + k8 + lt];
            pa[2] = Ps[(mb+lg  )*APAD + k8 + lt + 4];
            pa[3] = Ps[(mb+lg+8)*APAD + k8 + lt + 4];
            #pragma unroll
            for (int nt = 0; nt < 8; nt++) {
                uint32_t bfr[2];
                bfr[0] = Vs[(k8+lt  )*VPAD + nt*8 + lg];
                bfr[1] = Vs[(k8+lt+4)*VPAD + nt*8 + lg];
                mma_tf32(o[nt], pa, bfr);
            }
        }
        __syncthreads();   // before next tile overwrites Ks/Vs/Ps
    }

    // ---- normalize + write ctx ----
    const float inv0 = 1.f / li[0], inv1 = 1.f / li[1];
    #pragma unroll
    for (int nt = 0; nt < 8; nt++) {
        const int col = h*DHD + nt*8 + lt*2;
        *(float2*)(ctx + (size_t)(b*LSEQ + qrow[0])*DM + col) =
            make_float2(o[nt][0]*inv0, o[nt][1]*inv0);
        *(float2*)(ctx + (size_t)(b*LSEQ + qrow[1])*DM + col) =
            make_float2(o[nt][2]*inv1, o[nt][3]*inv1);
    }
}

// ---------------- launch ----------------
extern "C" void kernel_launch(void* const* d_in, const int* in_sizes, int n_in,
                              void* d_out, int out_size)
{
    (void)in_sizes; (void)n_in; (void)out_size;
    const float* x      = (const float*)d_in[0];
    const int*   amask  = (const int*)d_in[1];
    const float* adj    = (const float*)d_in[2];
    const float* Wf     = (const float*)d_in[3];
    const float* bf     = (const float*)d_in[4];
    const float* Wqkv   = (const float*)d_in[5];
    const float* bqkv   = (const float*)d_in[6];
    const float* Wo     = (const float*)d_in[7];
    const float* bo     = (const float*)d_in[8];
    const float* ln1g   = (const float*)d_in[9];
    const float* ln1b   = (const float*)d_in[10];
    const float* ln2g   = (const float*)d_in[11];
    const float* ln2b   = (const float*)d_in[12];
    const float* W1     = (const float*)d_in[13];
    const float* b1     = (const float*)d_in[14];
    const float* W2     = (const float*)d_in[15];
    const float* b2     = (const float*)d_in[16];
    const float* lscale = (const float*)d_in[17];
    float* out = (float*)d_out;

    float *gx, *gxn, *gqkv, *gctx, *gh;
    unsigned char* grow;
    cudaGetSymbolAddress((void**)&gx,   g_x);
    cudaGetSymbolAddress((void**)&gxn,  g_xn);
    cudaGetSymbolAddress((void**)&gqkv, g_qkv);
    cudaGetSymbolAddress((void**)&gctx, g_ctx);
    cudaGetSymbolAddress((void**)&gh,   g_h);
    cudaGetSymbolAddress((void**)&grow, g_rowall);

    cudaFuncSetAttribute((const void*)attn_mma,
                         cudaFuncAttributeMaxDynamicSharedMemorySize, ATTN_SMEM);

    // 1. fuse projection: g_x = x @ Wf^T + bf
    mma_gemm<0><<<dim3(DM/128, NTOK/128), 256>>>(x, Wf, bf, nullptr, gx, NTOK, DM, INDIM);
    // 2. row_all
    rowall_kernel<<<NTOK, 128>>>(amask, grow);
    // 3. LN1
    ln_kernel<<<NTOK, 128>>>(gx, ln1g, ln1b, gxn);
    // 4. qkv
    mma_gemm<0><<<dim3((3*DM)/128, NTOK/128), 256>>>(gxn, Wqkv, bqkv, nullptr, gqkv, NTOK, 3*DM, DM);
    // 5. attention (tensor pipe)
    attn_mma<<<dim3(LSEQ/64, NH, BB), 128, ATTN_SMEM>>>(gqkv, amask, adj, grow, lscale, gctx);
    // 6. out proj + residual
    mma_gemm<2><<<dim3(DM/128, NTOK/128), 256>>>(gctx, Wo, bo, gx, gx, NTOK, DM, DM);
    // 7. LN2
    ln_kernel<<<NTOK, 128>>>(gx, ln2g, ln2b, gxn);
    // 8. FFN up + GELU
    mma_gemm<1><<<dim3(FFD/128, NTOK/128), 256>>>(gxn, W1, b1, nullptr, gh, NTOK, FFD, DM);
    // 9. FFN down + residual -> out
    mma_gemm<2><<<dim3(DM/128, NTOK/128), 256>>>(gh, W2, b2, gx, out, NTOK, DM, FFD);
}

// round 8
// speedup vs baseline: 2.0311x; 1.3198x over previous
#include <cuda_runtime.h>
#include <math.h>
#include <stdint.h>

#define BB     4
#define LSEQ   1024
#define INDIM  256
#define DM     512
#define NH     8
#define DHD    64
#define FFD    2048
#define NTOK   (BB*LSEQ)   // 4096

// ---------------- scratch (device globals: allocation-free) ----------------
__device__ float g_x   [NTOK*DM];
__device__ float g_xn  [NTOK*DM];
__device__ float g_qkv [NTOK*3*DM];
__device__ float g_ctx [NTOK*DM];
__device__ float g_h   [NTOK*FFD];
__device__ unsigned char g_rowall[NTOK];
// tf32-pre-rounded GEMM inputs
__device__ float g_xr  [NTOK*INDIM];
__device__ float g_wf  [DM*INDIM];
__device__ float g_wqkv[3*DM*DM];
__device__ float g_wo  [DM*DM];
__device__ float g_w1  [FFD*DM];
__device__ float g_w2  [DM*FFD];

__device__ __forceinline__ uint32_t tf32r(float x) {
    uint32_t r; asm("cvt.rna.tf32.f32 %0, %1;" : "=r"(r) : "f"(x)); return r;
}
__device__ __forceinline__ float tf32f(float x) { return __uint_as_float(tf32r(x)); }
__device__ __forceinline__ void mma_tf32(float* c, const uint32_t* a, const uint32_t* b) {
    asm volatile(
        "mma.sync.aligned.m16n8k8.row.col.f32.tf32.tf32.f32 "
        "{%0,%1,%2,%3}, {%4,%5,%6,%7}, {%8,%9}, {%0,%1,%2,%3};"
        : "+f"(c[0]), "+f"(c[1]), "+f"(c[2]), "+f"(c[3])
        : "r"(a[0]), "r"(a[1]), "r"(a[2]), "r"(a[3]), "r"(b[0]), "r"(b[1]));
}
__device__ __forceinline__ uint32_t smem_u32(const void* p) {
    uint32_t a;
    asm("{ .reg .u64 t; cvta.to.shared.u64 t, %1; cvt.u32.u64 %0, t; }" : "=r"(a) : "l"(p));
    return a;
}
__device__ __forceinline__ void cpa16(uint32_t d, const void* s) {
    asm volatile("cp.async.ca.shared.global [%0], [%1], 16;" :: "r"(d), "l"(s));
}
__device__ __forceinline__ void cpa_commit() { asm volatile("cp.async.commit_group;" ::: "memory"); }
template<int N> __device__ __forceinline__ void cpa_wait() {
    asm volatile("cp.async.wait_group %0;" :: "n"(N) : "memory");
}

// ---------------- tf32 pre-round kernel (float4 grid-stride) ----------------
__global__ __launch_bounds__(256) void round_kernel(
    const float* __restrict__ src, float* __restrict__ dst, int n4)
{
    for (int i = blockIdx.x * 256 + threadIdx.x; i < n4; i += gridDim.x * 256) {
        float4 v = ((const float4*)src)[i];
        v.x = tf32f(v.x); v.y = tf32f(v.y); v.z = tf32f(v.z); v.w = tf32f(v.w);
        ((float4*)dst)[i] = v;
    }
}

// ================= tf32 mma.sync GEMM, cp.async 2-stage =================
// C[M,N] = A[M,K] @ W[N,K]^T + bias[N]  (EPI: 0=bias, 1=+GELU(round), 2=+residual)
// Inputs MUST be pre-rounded to tf32. BM=BN=128, BK=32; 8 warps 4(m)x2(n),
// warp tile 32x64. smem [row][k] pad 44 (16B-aligned rows, conflict-free frags).
#define RP   44
#define STGU (2 * 128 * RP)            // uints per stage (A then B)
#define GSMB (2 * STGU * 4)            // total dyn smem bytes (90112)

template<int EPI>
__global__ __launch_bounds__(256, 2) void mma_gemm(
    const float* __restrict__ A, const float* __restrict__ W,
    const float* __restrict__ bias, const float* __restrict__ res,
    float* __restrict__ C, int M, int N, int K)
{
    extern __shared__ uint32_t sm[];
    const uint32_t sbase = smem_u32(sm);
    const int tid = threadIdx.x;
    const int bm = blockIdx.y * 128, bn = blockIdx.x * 128;
    const int lane = tid & 31, warp = tid >> 5;
    const int wm = warp & 3, wn = warp >> 2;
    const int m_base = wm * 32, n_base = wn * 64;
    const int lg = lane >> 2, lt = lane & 3;

    float acc[2][8][4];
    #pragma unroll
    for (int mt = 0; mt < 2; mt++)
        #pragma unroll
        for (int nt = 0; nt < 8; nt++)
            #pragma unroll
            for (int q = 0; q < 4; q++) acc[mt][nt][q] = 0.f;

    // cp.async maps: 4 slots/thread for A, 4 for B. slot -> row=slot>>3, kc=slot&7
    const int row = tid >> 3, kc = tid & 7;   // base slot = tid; others +256 => row+32
    const float* Agp = A + (size_t)(bm + row) * K + kc * 4;
    const float* Bgp = W + (size_t)(bn + row) * K + kc * 4;
    const uint32_t sA_off = (row * RP + kc * 4) * 4;     // byte offset in stage
    const uint32_t rowstride = (size_t)32 * RP * 4;      // +32 rows in smem bytes
    const size_t gstride = (size_t)32 * K;               // +32 rows in global

    const int nc = K / 32;
    // prologue: chunk 0 -> stage 0
    {
        uint32_t sA = sbase + sA_off;
        uint32_t sB = sA + 128 * RP * 4;
        #pragma unroll
        for (int i = 0; i < 4; i++) {
            cpa16(sA + i * rowstride, Agp + i * gstride);
            cpa16(sB + i * rowstride, Bgp + i * gstride);
        }
        cpa_commit();
    }

    for (int c = 0; c < nc; c++) {
        const int st = c & 1;
        if (c + 1 < nc) {
            uint32_t sA = sbase + ((c + 1) & 1) * (STGU * 4) + sA_off;
            uint32_t sB = sA + 128 * RP * 4;
            const float* Ag = Agp + (c + 1) * 32;
            const float* Bg = Bgp + (c + 1) * 32;
            #pragma unroll
            for (int i = 0; i < 4; i++) {
                cpa16(sA + i * rowstride, Ag + i * gstride);
                cpa16(sB + i * rowstride, Bg + i * gstride);
            }
            cpa_commit();
            cpa_wait<1>();
        } else {
            cpa_wait<0>();
        }
        __syncthreads();

        const uint32_t* As = sm + st * STGU;
        const uint32_t* Bs = As + 128 * RP;
        #pragma unroll
        for (int ks = 0; ks < 4; ks++) {
            const int k = ks * 8;
            uint32_t a[2][4], b[8][2];
            #pragma unroll
            for (int mt = 0; mt < 2; mt++) {
                const int mr = m_base + mt * 16 + lg;
                a[mt][0] = As[mr * RP + k + lt];
                a[mt][1] = As[(mr + 8) * RP + k + lt];
                a[mt][2] = As[mr * RP + k + lt + 4];
                a[mt][3] = As[(mr + 8) * RP + k + lt + 4];
            }
            #pragma unroll
            for (int nt = 0; nt < 8; nt++) {
                const int nr = n_base + nt * 8 + lg;
                b[nt][0] = Bs[nr * RP + k + lt];
                b[nt][1] = Bs[nr * RP + k + lt + 4];
            }
            #pragma unroll
            for (int mt = 0; mt < 2; mt++)
                #pragma unroll
                for (int nt = 0; nt < 8; nt++)
                    mma_tf32(acc[mt][nt], a[mt], b[nt]);
        }
        __syncthreads();
    }

    #pragma unroll
    for (int mt = 0; mt < 2; mt++) {
        #pragma unroll
        for (int nt = 0; nt < 8; nt++) {
            const int rw = bm + m_base + mt * 16 + lg;
            const int col = bn + n_base + nt * 8 + lt * 2;
            #pragma unroll
            for (int half = 0; half < 2; half++) {
                const int r = rw + half * 8;
                float v0 = acc[mt][nt][half*2+0] + bias[col];
                float v1 = acc[mt][nt][half*2+1] + bias[col+1];
                if (EPI == 1) {
                    v0 = 0.5f * v0 * (1.f + erff(v0 * 0.70710678118654752f));
                    v1 = 0.5f * v1 * (1.f + erff(v1 * 0.70710678118654752f));
                    v0 = tf32f(v0); v1 = tf32f(v1);   // gh feeds W2 GEMM
                }
                if (EPI == 2) {
                    float2 rr = *(const float2*)(res + (size_t)r * N + col);
                    v0 += rr.x; v1 += rr.y;
                }
                *(float2*)(C + (size_t)r * N + col) = make_float2(v0, v1);
            }
        }
    }
}

// ---------------- layernorm (output pre-rounded to tf32) ----------------
__global__ __launch_bounds__(128) void ln_kernel(
    const float* __restrict__ X, const float* __restrict__ g,
    const float* __restrict__ b, float* __restrict__ Y)
{
    const int row = blockIdx.x;
    const int tid = threadIdx.x;
    float4 v = *(const float4*)(X + (size_t)row*DM + tid*4);
    float s  = v.x + v.y + v.z + v.w;
    float s2 = v.x*v.x + v.y*v.y + v.z*v.z + v.w*v.w;
    #pragma unroll
    for (int off = 16; off >= 1; off >>= 1) {
        s  += __shfl_xor_sync(0xffffffffu, s,  off);
        s2 += __shfl_xor_sync(0xffffffffu, s2, off);
    }
    __shared__ float sh[8];
    if ((tid & 31) == 0) { sh[tid>>5] = s; sh[4 + (tid>>5)] = s2; }
    __syncthreads();
    s  = sh[0] + sh[1] + sh[2] + sh[3];
    s2 = sh[4] + sh[5] + sh[6] + sh[7];
    float mu  = s * (1.f/DM);
    float var = s2 * (1.f/DM) - mu*mu;
    float inv = rsqrtf(var + 1e-5f);
    float4 gg = *(const float4*)(g + tid*4);
    float4 bb = *(const float4*)(b + tid*4);
    float4 y;
    y.x = tf32f((v.x - mu)*inv*gg.x + bb.x);
    y.y = tf32f((v.y - mu)*inv*gg.y + bb.y);
    y.z = tf32f((v.z - mu)*inv*gg.z + bb.z);
    y.w = tf32f((v.w - mu)*inv*gg.w + bb.w);
    *(float4*)(Y + (size_t)row*DM + tid*4) = y;
}

// ---------------- row_all (mask int32 0/1) ----------------
__global__ __launch_bounds__(128) void rowall_kernel(
    const int* __restrict__ mask, unsigned char* __restrict__ out)
{
    const int row = blockIdx.x;
    const int tid = threadIdx.x;
    const int* m = mask + (size_t)row * LSEQ;
    int mn = 1;
    #pragma unroll
    for (int c = 0; c < LSEQ / 512; c++) {
        int4 v = *(const int4*)(m + c*512 + tid*4);
        mn = min(mn, min(min(v.x, v.y), min(v.z, v.w)));
    }
    #pragma unroll
    for (int off = 16; off >= 1; off >>= 1)
        mn = min(mn, __shfl_xor_sync(0xffffffffu, mn, off));
    __shared__ int sh[4];
    if ((tid & 31) == 0) sh[tid>>5] = mn;
    __syncthreads();
    if (tid == 0) {
        int r = min(min(sh[0], sh[1]), min(sh[2], sh[3]));
        out[row] = (r != 0) ? 1 : 0;
    }
}

// ---------------- flash attention on tensor pipe (tf32 mma.sync) ----------------
#define APAD 68
#define VPAD 72
#define SM_Q 0
#define SM_K (64*APAD)
#define SM_P (2*64*APAD)
#define SM_V (3*64*APAD)
#define ATTN_SMEM ((3*64*APAD + 64*VPAD) * 4)

__global__ __launch_bounds__(128) void attn_mma(
    const float* __restrict__ qkv,
    const int* __restrict__ mask,
    const float* __restrict__ adj,
    const unsigned char* __restrict__ rowall,
    const float* __restrict__ logscale,
    float* __restrict__ ctx)
{
    extern __shared__ uint32_t sm[];
    uint32_t* Qs = sm + SM_Q;
    uint32_t* Ks = sm + SM_K;
    uint32_t* Ps = sm + SM_P;
    uint32_t* Vs = sm + SM_V;

    const int b = blockIdx.z, h = blockIdx.y;
    const int q0 = blockIdx.x * 64;
    const int tid = threadIdx.x;
    const int lane = tid & 31, warp = tid >> 5;
    const int lg = lane >> 2, lt = lane & 3;
    const int mb = warp * 16;
    const float escale = expf(logscale[0]);

    const int lrow = tid >> 1, lcb = (tid & 1) * 32;

    {
        const float* qg = qkv + (size_t)(b*LSEQ + q0 + lrow)*(3*DM) + h*DHD + lcb;
        #pragma unroll
        for (int i = 0; i < 8; i++) {
            float4 v = *(const float4*)(qg + i*4);
            uint32_t* dst = Qs + lrow*APAD + lcb + i*4;
            dst[0] = tf32r(v.x); dst[1] = tf32r(v.y);
            dst[2] = tf32r(v.z); dst[3] = tf32r(v.w);
        }
    }
    __syncthreads();

    uint32_t qa[8][4];
    #pragma unroll
    for (int ks = 0; ks < 8; ks++) {
        const int k8 = ks * 8;
        qa[ks][0] = Qs[(mb+lg  )*APAD + k8 + lt];
        qa[ks][1] = Qs[(mb+lg+8)*APAD + k8 + lt];
        qa[ks][2] = Qs[(mb+lg  )*APAD + k8 + lt + 4];
        qa[ks][3] = Qs[(mb+lg+8)*APAD + k8 + lt + 4];
    }

    float o[8][4];
    #pragma unroll
    for (int nt = 0; nt < 8; nt++)
        #pragma unroll
        for (int q = 0; q < 4; q++) o[nt][q] = 0.f;
    float mi[2] = {-1e30f, -1e30f}, li[2] = {0.f, 0.f};

    const int qrow[2] = { q0 + mb + lg, q0 + mb + lg + 8 };
    const bool raq[2] = { rowall[b*LSEQ + qrow[0]] != 0, rowall[b*LSEQ + qrow[1]] != 0 };

    for (int k0 = 0; k0 < LSEQ; k0 += 64) {
        {
            const float* kg = qkv + (size_t)(b*LSEQ + k0 + lrow)*(3*DM) + DM + h*DHD + lcb;
            const float* vg = kg + DM;
            #pragma unroll
            for (int i = 0; i < 8; i++) {
                float4 kv = *(const float4*)(kg + i*4);
                uint32_t* kd = Ks + lrow*APAD + lcb + i*4;
                kd[0] = tf32r(kv.x); kd[1] = tf32r(kv.y);
                kd[2] = tf32r(kv.z); kd[3] = tf32r(kv.w);
                float4 vv = *(const float4*)(vg + i*4);
                uint32_t* vd = Vs + lrow*VPAD + lcb + i*4;
                vd[0] = tf32r(vv.x); vd[1] = tf32r(vv.y);
                vd[2] = tf32r(vv.z); vd[3] = tf32r(vv.w);
            }
        }
        __syncthreads();

        float s[8][4];
        #pragma unroll
        for (int nt = 0; nt < 8; nt++)
            #pragma unroll
            for (int q = 0; q < 4; q++) s[nt][q] = 0.f;
        #pragma unroll
        for (int ks = 0; ks < 8; ks++) {
            const int k8 = ks * 8;
            #pragma unroll
            for (int nt = 0; nt < 8; nt++) {
                uint32_t bfr[2];
                bfr[0] = Ks[(nt*8+lg)*APAD + k8 + lt];
                bfr[1] = Ks[(nt*8+lg)*APAD + k8 + lt + 4];
                mma_tf32(s[nt], qa[ks], bfr);
            }
        }

        #pragma unroll
        for (int r = 0; r < 2; r++) {
            const int q = qrow[r];
            const size_t roff = ((size_t)b*LSEQ + q)*LSEQ + k0;
            float rmax = -1e30f;
            #pragma unroll
            for (int nt = 0; nt < 8; nt++) {
                const int col = nt*8 + lt*2;
                const int2 mm = *(const int2*)(mask + roff + col);
                const float2 ad = *(const float2*)(adj + roff + col);
                float a0 = fminf(fmaxf(ad.x, 0.f), 1.f);
                float a1 = fminf(fmaxf(ad.y, 0.f), 1.f);
                bool e0 = (mm.x != 0) && !((k0+col   == q) && raq[r]);
                bool e1 = (mm.y != 0) && !((k0+col+1 == q) && raq[r]);
                float v0 = s[nt][2*r  ]*0.125f + (e0 ? -10000.f : 0.f) + escale*a0;
                float v1 = s[nt][2*r+1]*0.125f + (e1 ? -10000.f : 0.f) + escale*a1;
                s[nt][2*r  ] = v0; s[nt][2*r+1] = v1;
                rmax = fmaxf(rmax, fmaxf(v0, v1));
            }
            rmax = fmaxf(rmax, __shfl_xor_sync(0xffffffffu, rmax, 1));
            rmax = fmaxf(rmax, __shfl_xor_sync(0xffffffffu, rmax, 2));
            float mnew = fmaxf(mi[r], rmax);
            float corr = __expf(mi[r] - mnew);
            float psum = 0.f;
            #pragma unroll
            for (int nt = 0; nt < 8; nt++) {
                float p0 = __expf(s[nt][2*r  ] - mnew);
                float p1 = __expf(s[nt][2*r+1] - mnew);
                s[nt][2*r] = p0; s[nt][2*r+1] = p1;
                psum += p0 + p1;
            }
            psum += __shfl_xor_sync(0xffffffffu, psum, 1);
            psum += __shfl_xor_sync(0xffffffffu, psum, 2);
            li[r] = li[r]*corr + psum;
            mi[r] = mnew;
            #pragma unroll
            for (int nt = 0; nt < 8; nt++) { o[nt][2*r] *= corr; o[nt][2*r+1] *= corr; }
            #pragma unroll
            for (int nt = 0; nt < 8; nt++) {
                uint32_t* pd = Ps + (mb+lg+8*r)*APAD + nt*8 + lt*2;
                pd[0] = tf32r(s[nt][2*r]); pd[1] = tf32r(s[nt][2*r+1]);
            }
        }
        __syncthreads();

        #pragma unroll
        for (int ks = 0; ks < 8; ks++) {
            const int k8 = ks * 8;
            uint32_t pa[4];
            pa[0] = Ps[(mb+lg  )*APAD + k8 + lt];
            pa[1] = Ps[(mb+lg+8)*APAD + k8 + lt];
            pa[2] = Ps[(mb+lg  )*APAD + k8 + lt + 4];
            pa[3] = Ps[(mb+lg+8)*APAD + k8 + lt + 4];
            #pragma unroll
            for (int nt = 0; nt < 8; nt++) {
                uint32_t bfr[2];
                bfr[0] = Vs[(k8+lt  )*VPAD + nt*8 + lg];
                bfr[1] = Vs[(k8+lt+4)*VPAD + nt*8 + lg];
                mma_tf32(o[nt], pa, bfr);
            }
        }
        __syncthreads();
    }

    const float inv0 = 1.f / li[0], inv1 = 1.f / li[1];
    #pragma unroll
    for (int nt = 0; nt < 8; nt++) {
        const int col = h*DHD + nt*8 + lt*2;
        *(float2*)(ctx + (size_t)(b*LSEQ + qrow[0])*DM + col) =
            make_float2(tf32f(o[nt][0]*inv0), tf32f(o[nt][1]*inv0));
        *(float2*)(ctx + (size_t)(b*LSEQ + qrow[1])*DM + col) =
            make_float2(tf32f(o[nt][2]*inv1), tf32f(o[nt][3]*inv1));
    }
}

// ---------------- launch ----------------
extern "C" void kernel_launch(void* const* d_in, const int* in_sizes, int n_in,
                              void* d_out, int out_size)
{
    (void)in_sizes; (void)n_in; (void)out_size;
    const float* x      = (const float*)d_in[0];
    const int*   amask  = (const int*)d_in[1];
    const float* adj    = (const float*)d_in[2];
    const float* Wf     = (const float*)d_in[3];
    const float* bf     = (const float*)d_in[4];
    const float* Wqkv   = (const float*)d_in[5];
    const float* bqkv   = (const float*)d_in[6];
    const float* Wo     = (const float*)d_in[7];
    const float* bo     = (const float*)d_in[8];
    const float* ln1g   = (const float*)d_in[9];
    const float* ln1b   = (const float*)d_in[10];
    const float* ln2g   = (const float*)d_in[11];
    const float* ln2b   = (const float*)d_in[12];
    const float* W1     = (const float*)d_in[13];
    const float* b1     = (const float*)d_in[14];
    const float* W2     = (const float*)d_in[15];
    const float* b2     = (const float*)d_in[16];
    const float* lscale = (const float*)d_in[17];
    float* out = (float*)d_out;

    float *gx, *gxn, *gqkv, *gctx, *gh;
    float *gxr, *gwf, *gwqkv, *gwo, *gw1, *gw2;
    unsigned char* grow;
    cudaGetSymbolAddress((void**)&gx,    g_x);
    cudaGetSymbolAddress((void**)&gxn,   g_xn);
    cudaGetSymbolAddress((void**)&gqkv,  g_qkv);
    cudaGetSymbolAddress((void**)&gctx,  g_ctx);
    cudaGetSymbolAddress((void**)&gh,    g_h);
    cudaGetSymbolAddress((void**)&grow,  g_rowall);
    cudaGetSymbolAddress((void**)&gxr,   g_xr);
    cudaGetSymbolAddress((void**)&gwf,   g_wf);
    cudaGetSymbolAddress((void**)&gwqkv, g_wqkv);
    cudaGetSymbolAddress((void**)&gwo,   g_wo);
    cudaGetSymbolAddress((void**)&gw1,   g_w1);
    cudaGetSymbolAddress((void**)&gw2,   g_w2);

    cudaFuncSetAttribute((const void*)mma_gemm<0>, cudaFuncAttributeMaxDynamicSharedMemorySize, GSMB);
    cudaFuncSetAttribute((const void*)mma_gemm<1>, cudaFuncAttributeMaxDynamicSharedMemorySize, GSMB);
    cudaFuncSetAttribute((const void*)mma_gemm<2>, cudaFuncAttributeMaxDynamicSharedMemorySize, GSMB);
    cudaFuncSetAttribute((const void*)attn_mma,    cudaFuncAttributeMaxDynamicSharedMemorySize, ATTN_SMEM);

    // 0. pre-round GEMM inputs to tf32 (bit-identical to in-kernel cvt)
    round_kernel<<<512, 256>>>(x,    gxr,   NTOK*INDIM/4);
    round_kernel<<<128, 256>>>(Wf,   gwf,   DM*INDIM/4);
    round_kernel<<<512, 256>>>(Wqkv, gwqkv, 3*DM*DM/4);
    round_kernel<<<256, 256>>>(Wo,   gwo,   DM*DM/4);
    round_kernel<<<512, 256>>>(W1,   gw1,   FFD*DM/4);
    round_kernel<<<512, 256>>>(W2,   gw2,   DM*FFD/4);

    // 1. fuse projection: g_x = x @ Wf^T + bf
    mma_gemm<0><<<dim3(DM/128, NTOK/128), 256, GSMB>>>(gxr, gwf, bf, nullptr, gx, NTOK, DM, INDIM);
    // 2. row_all
    rowall_kernel<<<NTOK, 128>>>(amask, grow);
    // 3. LN1 (tf32-rounded output)
    ln_kernel<<<NTOK, 128>>>(gx, ln1g, ln1b, gxn);
    // 4. qkv
    mma_gemm<0><<<dim3((3*DM)/128, NTOK/128), 256, GSMB>>>(gxn, gwqkv, bqkv, nullptr, gqkv, NTOK, 3*DM, DM);
    // 5. attention (tensor pipe; rounds its own Q/K/V and ctx output)
    attn_mma<<<dim3(LSEQ/64, NH, BB), 128, ATTN_SMEM>>>(gqkv, amask, adj, grow, lscale, gctx);
    // 6. out proj + residual
    mma_gemm<2><<<dim3(DM/128, NTOK/128), 256, GSMB>>>(gctx, gwo, bo, gx, gx, NTOK, DM, DM);
    // 7. LN2
    ln_kernel<<<NTOK, 128>>>(gx, ln2g, ln2b, gxn);
    // 8. FFN up + GELU (tf32-rounded output)
    mma_gemm<1><<<dim3(FFD/128, NTOK/128), 256, GSMB>>>(gxn, gw1, b1, nullptr, gh, NTOK, FFD, DM);
    // 9. FFN down + residual -> out
    mma_gemm<2><<<dim3(DM/128, NTOK/128), 256, GSMB>>>(gh, gw2, b2, gx, out, NTOK, DM, FFD);
}